// round 10
// baseline (speedup 1.0000x reference)
#include <cuda_runtime.h>
#include <cuda_bf16.h>
#include <cstdint>

// Problem constants
#define B 8
#define C 256
#define N 2304
#define TI 32
#define TJ 64
#define NTJ (N / TJ)   // 36

// ---------------- global scratch ----------------
__device__ __nv_bfloat16 g_Qb[(size_t)B * N * 32];   // [b][n][d]
__device__ __nv_bfloat16 g_Kb[(size_t)B * N * 32];   // [b][n][d]
__device__ __nv_bfloat16 g_Vb[(size_t)B * N * C];    // [b][n][c]

// ---------------- helpers ----------------
__device__ __forceinline__ uint32_t smem_u32(const void* p) {
    uint32_t a;
    asm("{ .reg .u64 t; cvta.to.shared.u64 t, %1; cvt.u32.u64 %0, t; }" : "=r"(a) : "l"(p));
    return a;
}
__device__ __forceinline__ void ldsm_x4(uint32_t* r, uint32_t addr) {
    asm volatile("ldmatrix.sync.aligned.m8n8.x4.shared.b16 {%0,%1,%2,%3}, [%4];"
                 : "=r"(r[0]), "=r"(r[1]), "=r"(r[2]), "=r"(r[3]) : "r"(addr));
}
__device__ __forceinline__ void ldsm_x4_t(uint32_t* r, uint32_t addr) {
    asm volatile("ldmatrix.sync.aligned.m8n8.x4.trans.shared.b16 {%0,%1,%2,%3}, [%4];"
                 : "=r"(r[0]), "=r"(r[1]), "=r"(r[2]), "=r"(r[3]) : "r"(addr));
}
__device__ __forceinline__ void ldsm_x2(uint32_t* r, uint32_t addr) {
    asm volatile("ldmatrix.sync.aligned.m8n8.x2.shared.b16 {%0,%1}, [%2];"
                 : "=r"(r[0]), "=r"(r[1]) : "r"(addr));
}
__device__ __forceinline__ void mma16816(float* c, const uint32_t* a, const uint32_t* b) {
    asm volatile("mma.sync.aligned.m16n8k16.row.col.f32.bf16.bf16.f32 "
                 "{%0,%1,%2,%3}, {%4,%5,%6,%7}, {%8,%9}, {%0,%1,%2,%3};"
                 : "+f"(c[0]), "+f"(c[1]), "+f"(c[2]), "+f"(c[3])
                 : "r"(a[0]), "r"(a[1]), "r"(a[2]), "r"(a[3]), "r"(b[0]), "r"(b[1]));
}
__device__ __forceinline__ uint32_t pack_bf16(float lo, float hi) {
    uint32_t r;
    asm("cvt.rn.bf16x2.f32 %0, %1, %2;" : "=r"(r) : "f"(hi), "f"(lo));
    return r;
}
__device__ __forceinline__ void cpa16(uint32_t saddr, const void* g) {
    asm volatile("cp.async.cg.shared.global [%0], [%1], 16;" :: "r"(saddr), "l"(g));
}
#define CP_COMMIT asm volatile("cp.async.commit_group;" ::: "memory")
#define CP_WAIT0  asm volatile("cp.async.wait_group 0;" ::: "memory")

// ---------------------------------------------------------------------------
// Projection via mma.sync (unchanged).
// ---------------------------------------------------------------------------
#define PJ_N 128
#define PJ_D 64
#define PJ_K 64
#define WSTR 528
#define XSTR 272
#define PJ_WS 0
#define PJ_XS (PJ_D * WSTR)     // 33792
#define PJ_SMEM (PJ_XS + PJ_K * XSTR)   // 51200

__global__ __launch_bounds__(256, 4) void proj_mma_kernel(
    const float* __restrict__ feat,
    const float* __restrict__ w1, const float* __restrict__ b1,
    const float* __restrict__ w2, const float* __restrict__ b2,
    const float* __restrict__ w3, const float* __restrict__ b3)
{
    extern __shared__ char sm[];
    const uint32_t smb = smem_u32(sm);
    const int tid = threadIdx.x;
    const int l   = tid & 31;
    const int w   = tid >> 5;
    const int b   = blockIdx.z;
    const int dt  = blockIdx.y;
    const int n0  = blockIdx.x * PJ_N;
    const int d0  = dt * PJ_D;

#pragma unroll
    for (int s = 0; s < 16; ++s) {
        int e    = tid + s * 256;
        int row  = e >> 6;
        int col4 = e & 63;
        int d = d0 + row;
        const float* wr;
        if (d < 32)      wr = w1 + d * C;
        else if (d < 64) wr = w2 + (d - 32) * C;
        else             wr = w3 + (d - 64) * C;
        float4 v = *(const float4*)(wr + col4 * 4);
        uint2 pk;
        pk.x = pack_bf16(v.x, v.y);
        pk.y = pack_bf16(v.z, v.w);
        *(uint2*)(sm + PJ_WS + row * WSTR + col4 * 8) = pk;
    }

    float acc[8][4];
#pragma unroll
    for (int nb = 0; nb < 8; ++nb)
#pragma unroll
        for (int q = 0; q < 4; ++q) acc[nb][q] = 0.f;

    for (int kc = 0; kc < 4; ++kc) {
        const int c0 = kc * PJ_K;
        __syncthreads();
#pragma unroll
        for (int s = 0; s < 8; ++s) {
            int e    = tid + s * 256;
            int row  = e >> 5;
            int col4 = e & 31;
            float4 v = *(const float4*)(feat + ((size_t)(b * C + c0 + row)) * N + n0 + col4 * 4);
            uint2 pk;
            pk.x = pack_bf16(v.x, v.y);
            pk.y = pack_bf16(v.z, v.w);
            *(uint2*)(sm + PJ_XS + row * XSTR + col4 * 8) = pk;
        }
        __syncthreads();

#pragma unroll
        for (int kk = 0; kk < 4; ++kk) {
            uint32_t a[4];
            {
                uint32_t addr = smb + PJ_XS
                    + (kk * 16 + (l >> 4) * 8 + (l & 7)) * XSTR
                    + (w * 16 + ((l >> 3) & 1) * 8) * 2;
                ldsm_x4_t(a, addr);
            }
#pragma unroll
            for (int nb = 0; nb < 8; ++nb) {
                uint32_t bfr[2];
                uint32_t addr = smb + PJ_WS
                    + (nb * 8 + (l & 7)) * WSTR
                    + (kc * 64 + kk * 16 + ((l >> 3) & 1) * 8) * 2;
                ldsm_x2(bfr, addr);
                mma16816(acc[nb], a, bfr);
            }
        }
    }

    const int nl0 = w * 16 + (l >> 2);
#pragma unroll
    for (int nb = 0; nb < 8; ++nb) {
        int gd = d0 + nb * 8 + (l & 3) * 2;
        float bias0, bias1;
        if (gd < 32)      { bias0 = b1[gd];      bias1 = b1[gd + 1]; }
        else if (gd < 64) { bias0 = b2[gd - 32]; bias1 = b2[gd - 31]; }
        else              { bias0 = b3[gd - 64]; bias1 = b3[gd - 63]; }
        uint32_t v0 = pack_bf16(acc[nb][0] + bias0, acc[nb][1] + bias1);
        uint32_t v1 = pack_bf16(acc[nb][2] + bias0, acc[nb][3] + bias1);
        size_t n_base = (size_t)(b * N) + n0 + nl0;
        if (gd < 32) {
            *(uint32_t*)(g_Qb + n_base * 32 + gd)       = v0;
            *(uint32_t*)(g_Qb + (n_base + 8) * 32 + gd) = v1;
        } else if (gd < 64) {
            *(uint32_t*)(g_Kb + n_base * 32 + gd - 32)       = v0;
            *(uint32_t*)(g_Kb + (n_base + 8) * 32 + gd - 32) = v1;
        } else {
            *(uint32_t*)(g_Vb + n_base * C + gd - 64)       = v0;
            *(uint32_t*)(g_Vb + (n_base + 8) * C + gd - 64) = v1;
        }
    }
}

// ---------------------------------------------------------------------------
// Fused flash attention, S computed once per (i-tile, b), TI=32 so 2 CTAs/SM.
// 256 threads = 8 warps: wr = w&1 (16-row group), wc = w>>1 (0..3).
// S phase: warp does rows 16wr x j-quarter wc -> exp -> P smem.
// PV phase: warp does rows 16wr x ch 64wc.
// ---------------------------------------------------------------------------
#define KSTR 80
#define VSTR 528                       // 256 ch bf16 + pad
#define PSTR 144                       // 64 j bf16 + 16B pad (multiple of 16)
#define KBUF (TJ * KSTR)               // 5120
#define VBUF (TJ * VSTR)               // 33792
#define SM_QS 0
#define SM_KS (TI * KSTR)              // 2560
#define SM_VS (SM_KS + 2 * KBUF)       // 12800
#define SM_PS (SM_VS + 2 * VBUF)       // 80384
#define SM_TOTAL (SM_PS + TI * PSTR)   // 84992

__global__ __launch_bounds__(256, 2) void attn_kernel(
    const float* __restrict__ feat,
    const float* __restrict__ gamma_p,
    float* __restrict__ out)
{
    extern __shared__ char sm[];
    const uint32_t smb = smem_u32(sm);
    const int tid = threadIdx.x;
    const int l   = tid & 31;
    const int w   = tid >> 5;
    const int wr  = w & 1;
    const int wc  = w >> 1;
    const int b   = blockIdx.y;
    const int i0  = blockIdx.x * TI;

    // ---- prologue: Q (plain, 32 rows), K0 (64 rows), V0 cp.async ----
    if (tid < 128) {
        int row = tid >> 2, seg = tid & 3;
        uint4 v = *(const uint4*)(g_Qb + ((size_t)(b * N) + i0 + row) * 32 + seg * 8);
        *(uint4*)(sm + SM_QS + row * KSTR + seg * 16) = v;
    }
    {
        int row = tid >> 2, seg = tid & 3;   // 64 rows x 4 segs
        cpa16(smb + SM_KS + row * KSTR + seg * 16,
              g_Kb + ((size_t)(b * N) + row) * 32 + seg * 8);
    }
#pragma unroll
    for (int k2 = 0; k2 < 8; ++k2) {
        int e = tid + k2 * 256;
        int vr = e >> 5, vs = e & 31;
        cpa16(smb + SM_VS + vr * VSTR + vs * 16,
              g_Vb + ((size_t)(b * N) + vr) * C + vs * 8);
    }
    CP_COMMIT;
    __syncthreads();   // Q visible

    // ---- hoist Q fragments (rows 16wr) ----
    uint32_t qa[2][4];
    {
        uint32_t qaddr = smb + SM_QS + (wr * 16 + (l & 15)) * KSTR + (l >> 4) * 16;
        ldsm_x4(qa[0], qaddr);
        ldsm_x4(qa[1], qaddr + 32);
    }

    float acc[8][4];
#pragma unroll
    for (int nb = 0; nb < 8; ++nb)
#pragma unroll
        for (int q = 0; q < 4; ++q) acc[nb][q] = 0.f;
    float l0 = 0.f, l1 = 0.f;

    // lane bases
    const uint32_t k_lane = smb + SM_KS
        + (wc * 16 + (l >> 4) * 8 + (l & 7)) * KSTR + ((l >> 3) & 1) * 16;
    const uint32_t v_lane = smb + SM_VS
        + (((l >> 3) & 1) * 8 + (l & 7)) * VSTR + wc * 128 + (l >> 4) * 16;
    const uint32_t p_ld   = smb + SM_PS + (wr * 16 + (l & 15)) * PSTR + (l >> 4) * 16;
    const uint32_t p_st   = smb + SM_PS + (wr * 16 + (l >> 2)) * PSTR + wc * 32 + (l & 3) * 4;

    for (int jt = 0; jt < NTJ; ++jt) {
        const int cur = jt & 1;
        CP_WAIT0;
        __syncthreads();               // K/V(jt) ready; P(jt-1) consumed

        if (jt + 1 < NTJ) {
            const int j0 = (jt + 1) * TJ;
            const int nxt = (jt + 1) & 1;
            {
                int row = tid >> 2, seg = tid & 3;
                cpa16(smb + SM_KS + nxt * KBUF + row * KSTR + seg * 16,
                      g_Kb + ((size_t)(b * N) + j0 + row) * 32 + seg * 8);
            }
#pragma unroll
            for (int k2 = 0; k2 < 8; ++k2) {
                int e = tid + k2 * 256;
                int vr = e >> 5, vs = e & 31;
                cpa16(smb + SM_VS + nxt * VBUF + vr * VSTR + vs * 16,
                      g_Vb + ((size_t)(b * N) + j0 + vr) * C + vs * 8);
            }
            CP_COMMIT;
        }

        // ---- S phase: rows 16wr x j-quarter wc ----
        float S[2][4];
#pragma unroll
        for (int nb = 0; nb < 2; ++nb)
#pragma unroll
            for (int q = 0; q < 4; ++q) S[nb][q] = 0.f;

        const uint32_t kcur = k_lane + cur * KBUF;
#pragma unroll
        for (int kb = 0; kb < 2; ++kb) {
            uint32_t kf[4];
            ldsm_x4(kf, kcur + kb * 32);
            mma16816(S[0], qa[kb], kf);
            mma16816(S[1], qa[kb], kf + 2);
        }

        // exp + row-sum partials + pack + store P quarter
        {
            float p00 = __expf(S[0][0]);
            float p01 = __expf(S[0][1]);
            float p02 = __expf(S[0][2]);
            float p03 = __expf(S[0][3]);
            float p10 = __expf(S[1][0]);
            float p11 = __expf(S[1][1]);
            float p12 = __expf(S[1][2]);
            float p13 = __expf(S[1][3]);
            l0 += p00 + p01 + p10 + p11;
            l1 += p02 + p03 + p12 + p13;
            *(uint32_t*)(sm + (p_st - smb))                 = pack_bf16(p00, p01);
            *(uint32_t*)(sm + (p_st - smb) + 8 * PSTR)      = pack_bf16(p02, p03);
            *(uint32_t*)(sm + (p_st - smb) + 16)            = pack_bf16(p10, p11);
            *(uint32_t*)(sm + (p_st - smb) + 8 * PSTR + 16) = pack_bf16(p12, p13);
        }
        __syncthreads();               // P(jt) visible

        // ---- PV phase: rows 16wr x ch 64wc ----
        const uint32_t vcur = v_lane + cur * VBUF;
#pragma unroll
        for (int kb2 = 0; kb2 < 4; ++kb2) {
            uint32_t pa[4];
            ldsm_x4(pa, p_ld + kb2 * 32);
#pragma unroll
            for (int nbp = 0; nbp < 4; ++nbp) {
                uint32_t vf[4];
                ldsm_x4_t(vf, vcur + kb2 * (16 * VSTR) + nbp * 32);
                mma16816(acc[nbp * 2 + 0], pa, vf);
                mma16816(acc[nbp * 2 + 1], pa, vf + 2);
            }
        }
    }

    // ---- l: in-warp shfl, then cross-wc reduction via smem ----
    float* lbuf = (float*)(sm + SM_PS);    // [4 wc][32 rows] (P dead)
    {
        l0 += __shfl_xor_sync(0xffffffffu, l0, 1);
        l0 += __shfl_xor_sync(0xffffffffu, l0, 2);
        l1 += __shfl_xor_sync(0xffffffffu, l1, 1);
        l1 += __shfl_xor_sync(0xffffffffu, l1, 2);
    }
    __syncthreads();                       // P reads done before overwrite
    if ((l & 3) == 0) {
        lbuf[wc * 32 + wr * 16 + (l >> 2)]     = l0;
        lbuf[wc * 32 + wr * 16 + (l >> 2) + 8] = l1;
    }
    __syncthreads();
    {
        const int r0 = wr * 16 + (l >> 2);
        float s0 = lbuf[r0] + lbuf[32 + r0] + lbuf[64 + r0] + lbuf[96 + r0];
        float s1 = lbuf[r0 + 8] + lbuf[32 + r0 + 8] + lbuf[64 + r0 + 8] + lbuf[96 + r0 + 8];
        const float gmma = gamma_p[0];
        const float inv0 = gmma / s0;
        const float inv1 = gmma / s1;
#pragma unroll
        for (int nb = 0; nb < 8; ++nb) {
            acc[nb][0] *= inv0;
            acc[nb][1] *= inv0;
            acc[nb][2] *= inv1;
            acc[nb][3] *= inv1;
        }
    }

    // ---- epilogue: 4 chunks of 64 ch, transpose through smem ----
    float* buf = (float*)(sm + SM_VS);     // 64 ch x 36 floats = 9216 B
    const int qr = l >> 2;
    const int qc = (l & 3) * 2;
#pragma unroll 1
    for (int cc = 0; cc < 4; ++cc) {
        __syncthreads();
        if (wc == cc) {
            const int ir = wr * 16 + qr;
#pragma unroll
            for (int nb = 0; nb < 8; ++nb) {
                int cl = nb * 8 + qc;
                buf[cl * 36 + ir]           = acc[nb][0];
                buf[(cl + 1) * 36 + ir]     = acc[nb][1];
                buf[cl * 36 + ir + 8]       = acc[nb][2];
                buf[(cl + 1) * 36 + ir + 8] = acc[nb][3];
            }
        }
        __syncthreads();
#pragma unroll
        for (int k2 = 0; k2 < 2; ++k2) {
            int e = tid + k2 * 256;        // 512 float4 = 64 ch x 8 segs
            int cl = e >> 3, seg = e & 7;
            float4 bv = *(float4*)(buf + cl * 36 + seg * 4);
            size_t g = ((size_t)(b * C + cc * 64 + cl)) * N + i0 + seg * 4;
            float4 fv = *(const float4*)(feat + g);
            float4 ov = {fv.x + bv.x, fv.y + bv.y, fv.z + bv.z, fv.w + bv.w};
            *(float4*)(out + g) = ov;
        }
    }
}

// ---------------------------------------------------------------------------
extern "C" void kernel_launch(void* const* d_in, const int* in_sizes, int n_in,
                              void* d_out, int out_size)
{
    const float* feat  = (const float*)d_in[0];
    const float* w1    = (const float*)d_in[1];
    const float* b1    = (const float*)d_in[2];
    const float* w2    = (const float*)d_in[3];
    const float* b2    = (const float*)d_in[4];
    const float* w3    = (const float*)d_in[5];
    const float* b3    = (const float*)d_in[6];
    const float* gamma = (const float*)d_in[7];
    float* out = (float*)d_out;

    cudaFuncSetAttribute(proj_mma_kernel, cudaFuncAttributeMaxDynamicSharedMemorySize, PJ_SMEM);
    proj_mma_kernel<<<dim3(N / PJ_N, 5, B), 256, PJ_SMEM>>>(feat, w1, b1, w2, b2, w3, b3);

    cudaFuncSetAttribute(attn_kernel, cudaFuncAttributeMaxDynamicSharedMemorySize, SM_TOTAL);
    attn_kernel<<<dim3(N / TI, B), 256, SM_TOTAL>>>(feat, gamma, out);
}

// round 11
// speedup vs baseline: 1.1357x; 1.1357x over previous
#include <cuda_runtime.h>
#include <cuda_bf16.h>
#include <cstdint>

// Problem constants
#define B 8
#define C 256
#define N 2304
#define TI 64
#define TJ 64
#define NTJ (N / TJ)   // 36

// ---------------- global scratch ----------------
__device__ __nv_bfloat16 g_Qb[(size_t)B * N * 32];   // [b][n][d]
__device__ __nv_bfloat16 g_Kb[(size_t)B * N * 32];   // [b][n][d]
__device__ __nv_bfloat16 g_Vb[(size_t)B * N * C];    // [b][n][c]

// ---------------- helpers ----------------
__device__ __forceinline__ uint32_t smem_u32(const void* p) {
    uint32_t a;
    asm("{ .reg .u64 t; cvta.to.shared.u64 t, %1; cvt.u32.u64 %0, t; }" : "=r"(a) : "l"(p));
    return a;
}
__device__ __forceinline__ void ldsm_x4(uint32_t* r, uint32_t addr) {
    asm volatile("ldmatrix.sync.aligned.m8n8.x4.shared.b16 {%0,%1,%2,%3}, [%4];"
                 : "=r"(r[0]), "=r"(r[1]), "=r"(r[2]), "=r"(r[3]) : "r"(addr));
}
__device__ __forceinline__ void ldsm_x4_t(uint32_t* r, uint32_t addr) {
    asm volatile("ldmatrix.sync.aligned.m8n8.x4.trans.shared.b16 {%0,%1,%2,%3}, [%4];"
                 : "=r"(r[0]), "=r"(r[1]), "=r"(r[2]), "=r"(r[3]) : "r"(addr));
}
__device__ __forceinline__ void ldsm_x2(uint32_t* r, uint32_t addr) {
    asm volatile("ldmatrix.sync.aligned.m8n8.x2.shared.b16 {%0,%1}, [%2];"
                 : "=r"(r[0]), "=r"(r[1]) : "r"(addr));
}
__device__ __forceinline__ void mma16816(float* c, const uint32_t* a, const uint32_t* b) {
    asm volatile("mma.sync.aligned.m16n8k16.row.col.f32.bf16.bf16.f32 "
                 "{%0,%1,%2,%3}, {%4,%5,%6,%7}, {%8,%9}, {%0,%1,%2,%3};"
                 : "+f"(c[0]), "+f"(c[1]), "+f"(c[2]), "+f"(c[3])
                 : "r"(a[0]), "r"(a[1]), "r"(a[2]), "r"(a[3]), "r"(b[0]), "r"(b[1]));
}
__device__ __forceinline__ uint32_t pack_bf16(float lo, float hi) {
    uint32_t r;
    asm("cvt.rn.bf16x2.f32 %0, %1, %2;" : "=r"(r) : "f"(hi), "f"(lo));
    return r;
}
__device__ __forceinline__ void cpa16(uint32_t saddr, const void* g) {
    asm volatile("cp.async.cg.shared.global [%0], [%1], 16;" :: "r"(saddr), "l"(g));
}
#define CP_COMMIT asm volatile("cp.async.commit_group;" ::: "memory")
#define CP_WAIT0  asm volatile("cp.async.wait_group 0;" ::: "memory")
#define CP_WAIT1  asm volatile("cp.async.wait_group 1;" ::: "memory")

// ---------------------------------------------------------------------------
// Projection via mma.sync (unchanged).
// ---------------------------------------------------------------------------
#define PJ_N 128
#define PJ_D 64
#define PJ_K 64
#define WSTR 528
#define XSTR 272
#define PJ_WS 0
#define PJ_XS (PJ_D * WSTR)     // 33792
#define PJ_SMEM (PJ_XS + PJ_K * XSTR)   // 51200

__global__ __launch_bounds__(256, 4) void proj_mma_kernel(
    const float* __restrict__ feat,
    const float* __restrict__ w1, const float* __restrict__ b1,
    const float* __restrict__ w2, const float* __restrict__ b2,
    const float* __restrict__ w3, const float* __restrict__ b3)
{
    extern __shared__ char sm[];
    const uint32_t smb = smem_u32(sm);
    const int tid = threadIdx.x;
    const int l   = tid & 31;
    const int w   = tid >> 5;
    const int b   = blockIdx.z;
    const int dt  = blockIdx.y;
    const int n0  = blockIdx.x * PJ_N;
    const int d0  = dt * PJ_D;

#pragma unroll
    for (int s = 0; s < 16; ++s) {
        int e    = tid + s * 256;
        int row  = e >> 6;
        int col4 = e & 63;
        int d = d0 + row;
        const float* wr;
        if (d < 32)      wr = w1 + d * C;
        else if (d < 64) wr = w2 + (d - 32) * C;
        else             wr = w3 + (d - 64) * C;
        float4 v = *(const float4*)(wr + col4 * 4);
        uint2 pk;
        pk.x = pack_bf16(v.x, v.y);
        pk.y = pack_bf16(v.z, v.w);
        *(uint2*)(sm + PJ_WS + row * WSTR + col4 * 8) = pk;
    }

    float acc[8][4];
#pragma unroll
    for (int nb = 0; nb < 8; ++nb)
#pragma unroll
        for (int q = 0; q < 4; ++q) acc[nb][q] = 0.f;

    for (int kc = 0; kc < 4; ++kc) {
        const int c0 = kc * PJ_K;
        __syncthreads();
#pragma unroll
        for (int s = 0; s < 8; ++s) {
            int e    = tid + s * 256;
            int row  = e >> 5;
            int col4 = e & 31;
            float4 v = *(const float4*)(feat + ((size_t)(b * C + c0 + row)) * N + n0 + col4 * 4);
            uint2 pk;
            pk.x = pack_bf16(v.x, v.y);
            pk.y = pack_bf16(v.z, v.w);
            *(uint2*)(sm + PJ_XS + row * XSTR + col4 * 8) = pk;
        }
        __syncthreads();

#pragma unroll
        for (int kk = 0; kk < 4; ++kk) {
            uint32_t a[4];
            {
                uint32_t addr = smb + PJ_XS
                    + (kk * 16 + (l >> 4) * 8 + (l & 7)) * XSTR
                    + (w * 16 + ((l >> 3) & 1) * 8) * 2;
                ldsm_x4_t(a, addr);
            }
#pragma unroll
            for (int nb = 0; nb < 8; ++nb) {
                uint32_t bfr[2];
                uint32_t addr = smb + PJ_WS
                    + (nb * 8 + (l & 7)) * WSTR
                    + (kc * 64 + kk * 16 + ((l >> 3) & 1) * 8) * 2;
                ldsm_x2(bfr, addr);
                mma16816(acc[nb], a, bfr);
            }
        }
    }

    const int nl0 = w * 16 + (l >> 2);
#pragma unroll
    for (int nb = 0; nb < 8; ++nb) {
        int gd = d0 + nb * 8 + (l & 3) * 2;
        float bias0, bias1;
        if (gd < 32)      { bias0 = b1[gd];      bias1 = b1[gd + 1]; }
        else if (gd < 64) { bias0 = b2[gd - 32]; bias1 = b2[gd - 31]; }
        else              { bias0 = b3[gd - 64]; bias1 = b3[gd - 63]; }
        uint32_t v0 = pack_bf16(acc[nb][0] + bias0, acc[nb][1] + bias1);
        uint32_t v1 = pack_bf16(acc[nb][2] + bias0, acc[nb][3] + bias1);
        size_t n_base = (size_t)(b * N) + n0 + nl0;
        if (gd < 32) {
            *(uint32_t*)(g_Qb + n_base * 32 + gd)       = v0;
            *(uint32_t*)(g_Qb + (n_base + 8) * 32 + gd) = v1;
        } else if (gd < 64) {
            *(uint32_t*)(g_Kb + n_base * 32 + gd - 32)       = v0;
            *(uint32_t*)(g_Kb + (n_base + 8) * 32 + gd - 32) = v1;
        } else {
            *(uint32_t*)(g_Vb + n_base * C + gd - 64)       = v0;
            *(uint32_t*)(g_Vb + (n_base + 8) * C + gd - 64) = v1;
        }
    }
}

// ---------------------------------------------------------------------------
// Fused flash attention, software-pipelined: ONE barrier per j-tile; each
// inter-barrier region runs S(jt) and PV(jt-1) (independent chains).
// K/V 4-slot, P 2-slot. 512 threads = 16 warps (wr 0..3, wc 0..3).
// ---------------------------------------------------------------------------
#define KSTR 80
#define VSTR 528                       // 256 ch bf16 + pad
#define PSTR 144                       // 64 j bf16 + 16B pad (multiple of 16)
#define KBUF (TJ * KSTR)               // 5120
#define VBUF (TJ * VSTR)               // 33792
#define PBUF (TI * PSTR)               // 9216
#define SM_QS 0
#define SM_KS (TI * KSTR)              // 5120  (4 slots)
#define SM_VS (SM_KS + 4 * KBUF)       // 25600 (4 slots)
#define SM_PS (SM_VS + 4 * VBUF)       // 160768 (2 slots)
#define SM_TOTAL (SM_PS + 2 * PBUF)    // 179200

__device__ __forceinline__ void kv_prefetch(uint32_t smb, int b, int jt, int tid) {
    const int j0 = jt * TJ;
    if (tid < 256) {
        int row = tid >> 2, seg = tid & 3;
        cpa16(smb + SM_KS + (jt & 3) * KBUF + row * KSTR + seg * 16,
              g_Kb + ((size_t)(b * N) + j0 + row) * 32 + seg * 8);
    }
    const uint32_t vbase = smb + SM_VS + (jt & 3) * VBUF;
#pragma unroll
    for (int k2 = 0; k2 < 4; ++k2) {
        int e = tid + k2 * 512;
        int vr = e >> 5, vs = e & 31;
        cpa16(vbase + vr * VSTR + vs * 16,
              g_Vb + ((size_t)(b * N) + j0 + vr) * C + vs * 8);
    }
    CP_COMMIT;
}

__global__ __launch_bounds__(512, 1) void attn_kernel(
    const float* __restrict__ feat,
    const float* __restrict__ gamma_p,
    float* __restrict__ out)
{
    extern __shared__ char sm[];
    const uint32_t smb = smem_u32(sm);
    const int tid = threadIdx.x;
    const int l   = tid & 31;
    const int w   = tid >> 5;
    const int wr  = w & 3;
    const int wc  = w >> 2;
    const int b   = blockIdx.y;
    const int i0  = blockIdx.x * TI;

    // ---- prologue: Q plain store, KV(0), KV(1) async ----
    if (tid < 256) {
        int row = tid >> 2, seg = tid & 3;
        uint4 v = *(const uint4*)(g_Qb + ((size_t)(b * N) + i0 + row) * 32 + seg * 8);
        *(uint4*)(sm + SM_QS + row * KSTR + seg * 16) = v;
    }
    kv_prefetch(smb, b, 0, tid);
    kv_prefetch(smb, b, 1, tid);
    __syncthreads();   // Q visible

    uint32_t qa[2][4];
    {
        uint32_t qaddr = smb + SM_QS + (wr * 16 + (l & 15)) * KSTR + (l >> 4) * 16;
        ldsm_x4(qa[0], qaddr);
        ldsm_x4(qa[1], qaddr + 32);
    }
    CP_WAIT1;          // group 0 (KV0) complete per-thread; loop-top barrier gives CTA visibility

    float acc[8][4];
#pragma unroll
    for (int nb = 0; nb < 8; ++nb)
#pragma unroll
        for (int q = 0; q < 4; ++q) acc[nb][q] = 0.f;
    float l0 = 0.f, l1 = 0.f;

    // lane offsets (within a slot)
    const uint32_t k_off = (wc * 16 + (l >> 4) * 8 + (l & 7)) * KSTR + ((l >> 3) & 1) * 16;
    const uint32_t v_off = (((l >> 3) & 1) * 8 + (l & 7)) * VSTR + wc * 128 + (l >> 4) * 16;
    const uint32_t pl_off = (wr * 16 + (l & 15)) * PSTR + (l >> 4) * 16;
    const uint32_t ps_off = (wr * 16 + (l >> 2)) * PSTR + wc * 32 + (l & 3) * 4;

    for (int jt = 0; jt <= NTJ; ++jt) {
        __syncthreads();   // makes visible: KV waited last iter, P stored last iter;
                           // orders: PV(jt-2)/S(jt-2) reads before prefetch overwrite

        if (jt + 2 < NTJ) kv_prefetch(smb, b, jt + 2, tid);

        // ---- S(jt): rows 16wr x j-quarter wc -> exp -> P slot jt&1 ----
        if (jt < NTJ) {
            float S[2][4];
#pragma unroll
            for (int nb = 0; nb < 2; ++nb)
#pragma unroll
                for (int q = 0; q < 4; ++q) S[nb][q] = 0.f;

            const uint32_t kcur = smb + SM_KS + (jt & 3) * KBUF + k_off;
#pragma unroll
            for (int kb = 0; kb < 2; ++kb) {
                uint32_t kf[4];
                ldsm_x4(kf, kcur + kb * 32);
                mma16816(S[0], qa[kb], kf);
                mma16816(S[1], qa[kb], kf + 2);
            }

            float p00 = __expf(S[0][0]);
            float p01 = __expf(S[0][1]);
            float p02 = __expf(S[0][2]);
            float p03 = __expf(S[0][3]);
            float p10 = __expf(S[1][0]);
            float p11 = __expf(S[1][1]);
            float p12 = __expf(S[1][2]);
            float p13 = __expf(S[1][3]);
            l0 += p00 + p01 + p10 + p11;
            l1 += p02 + p03 + p12 + p13;
            const uint32_t pst = SM_PS + (jt & 1) * PBUF + ps_off;
            *(uint32_t*)(sm + pst)                 = pack_bf16(p00, p01);
            *(uint32_t*)(sm + pst + 8 * PSTR)      = pack_bf16(p02, p03);
            *(uint32_t*)(sm + pst + 16)            = pack_bf16(p10, p11);
            *(uint32_t*)(sm + pst + 8 * PSTR + 16) = pack_bf16(p12, p13);
        }

        // ---- PV(jt-1): rows 16wr x ch 64wc ----
        if (jt >= 1) {
            const uint32_t vcur = smb + SM_VS + ((jt - 1) & 3) * VBUF + v_off;
            const uint32_t pld  = smb + SM_PS + ((jt - 1) & 1) * PBUF + pl_off;
#pragma unroll
            for (int kb2 = 0; kb2 < 4; ++kb2) {
                uint32_t pa[4];
                ldsm_x4(pa, pld + kb2 * 32);
#pragma unroll
                for (int nbp = 0; nbp < 4; ++nbp) {
                    uint32_t vf[4];
                    ldsm_x4_t(vf, vcur + kb2 * (16 * VSTR) + nbp * 32);
                    mma16816(acc[nbp * 2 + 0], pa, vf);
                    mma16816(acc[nbp * 2 + 1], pa, vf + 2);
                }
            }
        }

        // ensure group jt+1 complete (per-thread) before next barrier
        if (jt + 1 < NTJ) {
            if (jt + 2 < NTJ) { CP_WAIT1; } else { CP_WAIT0; }
        }
    }

    // ---- l: in-warp shfl, then cross-wc reduction via smem ----
    float* lbuf = (float*)(sm + SM_PS);    // [4 wc][64 rows] (P dead)
    {
        l0 += __shfl_xor_sync(0xffffffffu, l0, 1);
        l0 += __shfl_xor_sync(0xffffffffu, l0, 2);
        l1 += __shfl_xor_sync(0xffffffffu, l1, 1);
        l1 += __shfl_xor_sync(0xffffffffu, l1, 2);
    }
    __syncthreads();                       // P reads done before overwrite
    if ((l & 3) == 0) {
        lbuf[wc * 64 + wr * 16 + (l >> 2)]     = l0;
        lbuf[wc * 64 + wr * 16 + (l >> 2) + 8] = l1;
    }
    __syncthreads();
    {
        const int r0 = wr * 16 + (l >> 2);
        float s0 = lbuf[r0] + lbuf[64 + r0] + lbuf[128 + r0] + lbuf[192 + r0];
        float s1 = lbuf[r0 + 8] + lbuf[64 + r0 + 8] + lbuf[128 + r0 + 8] + lbuf[192 + r0 + 8];
        const float gmma = gamma_p[0];
        const float inv0 = gmma / s0;
        const float inv1 = gmma / s1;
#pragma unroll
        for (int nb = 0; nb < 8; ++nb) {
            acc[nb][0] *= inv0;
            acc[nb][1] *= inv0;
            acc[nb][2] *= inv1;
            acc[nb][3] *= inv1;
        }
    }

    // ---- epilogue: 4 chunks of 64 ch, transpose through smem ----
    float* buf = (float*)(sm + SM_VS);     // 64 x 68 floats
    const int qr = l >> 2;
    const int qc = (l & 3) * 2;
#pragma unroll 1
    for (int cc = 0; cc < 4; ++cc) {
        __syncthreads();
        if (wc == cc) {
            const int ir = wr * 16 + qr;
#pragma unroll
            for (int nb = 0; nb < 8; ++nb) {
                int cl = nb * 8 + qc;
                buf[cl * 68 + ir]           = acc[nb][0];
                buf[(cl + 1) * 68 + ir]     = acc[nb][1];
                buf[cl * 68 + ir + 8]       = acc[nb][2];
                buf[(cl + 1) * 68 + ir + 8] = acc[nb][3];
            }
        }
        __syncthreads();
#pragma unroll
        for (int k2 = 0; k2 < 2; ++k2) {
            int e = tid + k2 * 512;
            int cl = e >> 4, seg = e & 15;
            float4 bv = *(float4*)(buf + cl * 68 + seg * 4);
            size_t g = ((size_t)(b * C + cc * 64 + cl)) * N + i0 + seg * 4;
            float4 fv = *(const float4*)(feat + g);
            float4 ov = {fv.x + bv.x, fv.y + bv.y, fv.z + bv.z, fv.w + bv.w};
            *(float4*)(out + g) = ov;
        }
    }
}

// ---------------------------------------------------------------------------
extern "C" void kernel_launch(void* const* d_in, const int* in_sizes, int n_in,
                              void* d_out, int out_size)
{
    const float* feat  = (const float*)d_in[0];
    const float* w1    = (const float*)d_in[1];
    const float* b1    = (const float*)d_in[2];
    const float* w2    = (const float*)d_in[3];
    const float* b2    = (const float*)d_in[4];
    const float* w3    = (const float*)d_in[5];
    const float* b3    = (const float*)d_in[6];
    const float* gamma = (const float*)d_in[7];
    float* out = (float*)d_out;

    cudaFuncSetAttribute(proj_mma_kernel, cudaFuncAttributeMaxDynamicSharedMemorySize, PJ_SMEM);
    proj_mma_kernel<<<dim3(N / PJ_N, 5, B), 256, PJ_SMEM>>>(feat, w1, b1, w2, b2, w3, b3);

    cudaFuncSetAttribute(attn_kernel, cudaFuncAttributeMaxDynamicSharedMemorySize, SM_TOTAL);
    attn_kernel<<<dim3(N / TI, B), 512, SM_TOTAL>>>(feat, gamma, out);
}

// round 12
// speedup vs baseline: 1.1615x; 1.0227x over previous
#include <cuda_runtime.h>
#include <cuda_bf16.h>
#include <cstdint>

// Problem constants
#define B 8
#define C 256
#define N 2304
#define TI 64
#define TJ 64
#define NTJ (N / TJ)   // 36

// ---------------- global scratch ----------------
__device__ __nv_bfloat16 g_Qb[(size_t)B * N * 32];   // [b][n][d]
__device__ __nv_bfloat16 g_Kb[(size_t)B * N * 32];   // [b][n][d]
__device__ __nv_bfloat16 g_Vb[(size_t)B * N * C];    // [b][n][c]

// ---------------- helpers ----------------
__device__ __forceinline__ uint32_t smem_u32(const void* p) {
    uint32_t a;
    asm("{ .reg .u64 t; cvta.to.shared.u64 t, %1; cvt.u32.u64 %0, t; }" : "=r"(a) : "l"(p));
    return a;
}
__device__ __forceinline__ void ldsm_x4(uint32_t* r, uint32_t addr) {
    asm volatile("ldmatrix.sync.aligned.m8n8.x4.shared.b16 {%0,%1,%2,%3}, [%4];"
                 : "=r"(r[0]), "=r"(r[1]), "=r"(r[2]), "=r"(r[3]) : "r"(addr));
}
__device__ __forceinline__ void ldsm_x4_t(uint32_t* r, uint32_t addr) {
    asm volatile("ldmatrix.sync.aligned.m8n8.x4.trans.shared.b16 {%0,%1,%2,%3}, [%4];"
                 : "=r"(r[0]), "=r"(r[1]), "=r"(r[2]), "=r"(r[3]) : "r"(addr));
}
__device__ __forceinline__ void ldsm_x2(uint32_t* r, uint32_t addr) {
    asm volatile("ldmatrix.sync.aligned.m8n8.x2.shared.b16 {%0,%1}, [%2];"
                 : "=r"(r[0]), "=r"(r[1]) : "r"(addr));
}
__device__ __forceinline__ void mma16816(float* c, const uint32_t* a, const uint32_t* b) {
    asm volatile("mma.sync.aligned.m16n8k16.row.col.f32.bf16.bf16.f32 "
                 "{%0,%1,%2,%3}, {%4,%5,%6,%7}, {%8,%9}, {%0,%1,%2,%3};"
                 : "+f"(c[0]), "+f"(c[1]), "+f"(c[2]), "+f"(c[3])
                 : "r"(a[0]), "r"(a[1]), "r"(a[2]), "r"(a[3]), "r"(b[0]), "r"(b[1]));
}
__device__ __forceinline__ uint32_t pack_bf16(float lo, float hi) {
    uint32_t r;
    asm("cvt.rn.bf16x2.f32 %0, %1, %2;" : "=r"(r) : "f"(hi), "f"(lo));
    return r;
}
__device__ __forceinline__ void cpa16(uint32_t saddr, const void* g) {
    asm volatile("cp.async.cg.shared.global [%0], [%1], 16;" :: "r"(saddr), "l"(g));
}
#define CP_COMMIT asm volatile("cp.async.commit_group;" ::: "memory")
#define CP_WAIT0  asm volatile("cp.async.wait_group 0;" ::: "memory")
#define CP_WAIT1  asm volatile("cp.async.wait_group 1;" ::: "memory")

// ---------------------------------------------------------------------------
// Merged projection: one CTA per (n-tile, batch) loads X[256c x 128n] ONCE,
// then loops all 5 d-tiles staging only W. feat DRAM traffic / 5.
// ---------------------------------------------------------------------------
#define PJ_N 128
#define WSTR 528                // 256 bf16 + 8 pad (bytes)
#define XSTR 272                // 128 bf16 + 8 pad (bytes)
#define PJ_WS 0
#define PJ_XS (64 * WSTR)       // 33792
#define PJ_SMEM (PJ_XS + C * XSTR)   // 33792 + 69632 = 103424

__global__ __launch_bounds__(256, 2) void proj_mma_kernel(
    const float* __restrict__ feat,
    const float* __restrict__ w1, const float* __restrict__ b1,
    const float* __restrict__ w2, const float* __restrict__ b2,
    const float* __restrict__ w3, const float* __restrict__ b3)
{
    extern __shared__ char sm[];
    const uint32_t smb = smem_u32(sm);
    const int tid = threadIdx.x;
    const int l   = tid & 31;
    const int w   = tid >> 5;
    const int b   = blockIdx.y;
    const int n0  = blockIdx.x * PJ_N;

    // ---- load X tile [256 c][128 n] fp32 -> bf16 smem (ONCE) ----
#pragma unroll
    for (int s = 0; s < 32; ++s) {
        int e    = tid + s * 256;       // 0..8191 float4 chunks
        int row  = e >> 5;              // c 0..255
        int col4 = e & 31;              // float4 index in 128-n row
        float4 v = *(const float4*)(feat + ((size_t)(b * C + row)) * N + n0 + col4 * 4);
        uint2 pk;
        pk.x = pack_bf16(v.x, v.y);
        pk.y = pack_bf16(v.z, v.w);
        *(uint2*)(sm + PJ_XS + row * XSTR + col4 * 8) = pk;
    }

    for (int dt = 0; dt < 5; ++dt) {
        const int d0 = dt * 64;
        __syncthreads();                // protect W from previous dt's readers
        // ---- load W tile [64 d][256 c] fp32 -> bf16 smem ----
#pragma unroll
        for (int s = 0; s < 16; ++s) {
            int e    = tid + s * 256;
            int row  = e >> 6;
            int col4 = e & 63;
            int d = d0 + row;
            const float* wr;
            if (d < 32)      wr = w1 + d * C;
            else if (d < 64) wr = w2 + (d - 32) * C;
            else             wr = w3 + (d - 64) * C;
            float4 v = *(const float4*)(wr + col4 * 4);
            uint2 pk;
            pk.x = pack_bf16(v.x, v.y);
            pk.y = pack_bf16(v.z, v.w);
            *(uint2*)(sm + PJ_WS + row * WSTR + col4 * 8) = pk;
        }
        __syncthreads();

        float acc[8][4];
#pragma unroll
        for (int nb = 0; nb < 8; ++nb)
#pragma unroll
            for (int q = 0; q < 4; ++q) acc[nb][q] = 0.f;

#pragma unroll
        for (int kc = 0; kc < 4; ++kc) {
#pragma unroll
            for (int kk = 0; kk < 4; ++kk) {
                uint32_t a[4];
                {
                    uint32_t addr = smb + PJ_XS
                        + (kc * 64 + kk * 16 + (l >> 4) * 8 + (l & 7)) * XSTR
                        + (w * 16 + ((l >> 3) & 1) * 8) * 2;
                    ldsm_x4_t(a, addr);
                }
#pragma unroll
                for (int nb = 0; nb < 8; ++nb) {
                    uint32_t bfr[2];
                    uint32_t addr = smb + PJ_WS
                        + (nb * 8 + (l & 7)) * WSTR
                        + (kc * 64 + kk * 16 + ((l >> 3) & 1) * 8) * 2;
                    ldsm_x2(bfr, addr);
                    mma16816(acc[nb], a, bfr);
                }
            }
        }

        // ---- bias + store ----
        const int nl0 = w * 16 + (l >> 2);
#pragma unroll
        for (int nb = 0; nb < 8; ++nb) {
            int gd = d0 + nb * 8 + (l & 3) * 2;
            float bias0, bias1;
            if (gd < 32)      { bias0 = b1[gd];      bias1 = b1[gd + 1]; }
            else if (gd < 64) { bias0 = b2[gd - 32]; bias1 = b2[gd - 31]; }
            else              { bias0 = b3[gd - 64]; bias1 = b3[gd - 63]; }
            uint32_t v0 = pack_bf16(acc[nb][0] + bias0, acc[nb][1] + bias1);
            uint32_t v1 = pack_bf16(acc[nb][2] + bias0, acc[nb][3] + bias1);
            size_t n_base = (size_t)(b * N) + n0 + nl0;
            if (gd < 32) {
                *(uint32_t*)(g_Qb + n_base * 32 + gd)       = v0;
                *(uint32_t*)(g_Qb + (n_base + 8) * 32 + gd) = v1;
            } else if (gd < 64) {
                *(uint32_t*)(g_Kb + n_base * 32 + gd - 32)       = v0;
                *(uint32_t*)(g_Kb + (n_base + 8) * 32 + gd - 32) = v1;
            } else {
                *(uint32_t*)(g_Vb + n_base * C + gd - 64)       = v0;
                *(uint32_t*)(g_Vb + (n_base + 8) * C + gd - 64) = v1;
            }
        }
    }
}

// ---------------------------------------------------------------------------
// Fused flash attention (unchanged from Round 11): software-pipelined, one
// barrier per j-tile, S(jt) + PV(jt-1) fused. K/V 4-slot, P 2-slot.
// ---------------------------------------------------------------------------
#define KSTR 80
#define VSTR 528                       // 256 ch bf16 + pad
#define PSTR 144                       // 64 j bf16 + 16B pad (multiple of 16)
#define KBUF (TJ * KSTR)               // 5120
#define VBUF (TJ * VSTR)               // 33792
#define PBUF (TI * PSTR)               // 9216
#define SM_QS 0
#define SM_KS (TI * KSTR)              // 5120  (4 slots)
#define SM_VS (SM_KS + 4 * KBUF)       // 25600 (4 slots)
#define SM_PS (SM_VS + 4 * VBUF)       // 160768 (2 slots)
#define SM_TOTAL (SM_PS + 2 * PBUF)    // 179200

__device__ __forceinline__ void kv_prefetch(uint32_t smb, int b, int jt, int tid) {
    const int j0 = jt * TJ;
    if (tid < 256) {
        int row = tid >> 2, seg = tid & 3;
        cpa16(smb + SM_KS + (jt & 3) * KBUF + row * KSTR + seg * 16,
              g_Kb + ((size_t)(b * N) + j0 + row) * 32 + seg * 8);
    }
    const uint32_t vbase = smb + SM_VS + (jt & 3) * VBUF;
#pragma unroll
    for (int k2 = 0; k2 < 4; ++k2) {
        int e = tid + k2 * 512;
        int vr = e >> 5, vs = e & 31;
        cpa16(vbase + vr * VSTR + vs * 16,
              g_Vb + ((size_t)(b * N) + j0 + vr) * C + vs * 8);
    }
    CP_COMMIT;
}

__global__ __launch_bounds__(512, 1) void attn_kernel(
    const float* __restrict__ feat,
    const float* __restrict__ gamma_p,
    float* __restrict__ out)
{
    extern __shared__ char sm[];
    const uint32_t smb = smem_u32(sm);
    const int tid = threadIdx.x;
    const int l   = tid & 31;
    const int w   = tid >> 5;
    const int wr  = w & 3;
    const int wc  = w >> 2;
    const int b   = blockIdx.y;
    const int i0  = blockIdx.x * TI;

    // ---- prologue: Q plain store, KV(0), KV(1) async ----
    if (tid < 256) {
        int row = tid >> 2, seg = tid & 3;
        uint4 v = *(const uint4*)(g_Qb + ((size_t)(b * N) + i0 + row) * 32 + seg * 8);
        *(uint4*)(sm + SM_QS + row * KSTR + seg * 16) = v;
    }
    kv_prefetch(smb, b, 0, tid);
    kv_prefetch(smb, b, 1, tid);
    __syncthreads();   // Q visible

    uint32_t qa[2][4];
    {
        uint32_t qaddr = smb + SM_QS + (wr * 16 + (l & 15)) * KSTR + (l >> 4) * 16;
        ldsm_x4(qa[0], qaddr);
        ldsm_x4(qa[1], qaddr + 32);
    }
    CP_WAIT1;          // KV(0) complete per-thread; loop-top barrier gives CTA visibility

    float acc[8][4];
#pragma unroll
    for (int nb = 0; nb < 8; ++nb)
#pragma unroll
        for (int q = 0; q < 4; ++q) acc[nb][q] = 0.f;
    float l0 = 0.f, l1 = 0.f;

    // lane offsets (within a slot)
    const uint32_t k_off = (wc * 16 + (l >> 4) * 8 + (l & 7)) * KSTR + ((l >> 3) & 1) * 16;
    const uint32_t v_off = (((l >> 3) & 1) * 8 + (l & 7)) * VSTR + wc * 128 + (l >> 4) * 16;
    const uint32_t pl_off = (wr * 16 + (l & 15)) * PSTR + (l >> 4) * 16;
    const uint32_t ps_off = (wr * 16 + (l >> 2)) * PSTR + wc * 32 + (l & 3) * 4;

    for (int jt = 0; jt <= NTJ; ++jt) {
        __syncthreads();   // KV(jt) + P(jt-1) visible; prior reads ordered before overwrite

        if (jt + 2 < NTJ) kv_prefetch(smb, b, jt + 2, tid);

        // ---- S(jt): rows 16wr x j-quarter wc -> exp -> P slot jt&1 ----
        if (jt < NTJ) {
            float S[2][4];
#pragma unroll
            for (int nb = 0; nb < 2; ++nb)
#pragma unroll
                for (int q = 0; q < 4; ++q) S[nb][q] = 0.f;

            const uint32_t kcur = smb + SM_KS + (jt & 3) * KBUF + k_off;
#pragma unroll
            for (int kb = 0; kb < 2; ++kb) {
                uint32_t kf[4];
                ldsm_x4(kf, kcur + kb * 32);
                mma16816(S[0], qa[kb], kf);
                mma16816(S[1], qa[kb], kf + 2);
            }

            float p00 = __expf(S[0][0]);
            float p01 = __expf(S[0][1]);
            float p02 = __expf(S[0][2]);
            float p03 = __expf(S[0][3]);
            float p10 = __expf(S[1][0]);
            float p11 = __expf(S[1][1]);
            float p12 = __expf(S[1][2]);
            float p13 = __expf(S[1][3]);
            l0 += p00 + p01 + p10 + p11;
            l1 += p02 + p03 + p12 + p13;
            const uint32_t pst = SM_PS + (jt & 1) * PBUF + ps_off;
            *(uint32_t*)(sm + pst)                 = pack_bf16(p00, p01);
            *(uint32_t*)(sm + pst + 8 * PSTR)      = pack_bf16(p02, p03);
            *(uint32_t*)(sm + pst + 16)            = pack_bf16(p10, p11);
            *(uint32_t*)(sm + pst + 8 * PSTR + 16) = pack_bf16(p12, p13);
        }

        // ---- PV(jt-1): rows 16wr x ch 64wc ----
        if (jt >= 1) {
            const uint32_t vcur = smb + SM_VS + ((jt - 1) & 3) * VBUF + v_off;
            const uint32_t pld  = smb + SM_PS + ((jt - 1) & 1) * PBUF + pl_off;
#pragma unroll
            for (int kb2 = 0; kb2 < 4; ++kb2) {
                uint32_t pa[4];
                ldsm_x4(pa, pld + kb2 * 32);
#pragma unroll
                for (int nbp = 0; nbp < 4; ++nbp) {
                    uint32_t vf[4];
                    ldsm_x4_t(vf, vcur + kb2 * (16 * VSTR) + nbp * 32);
                    mma16816(acc[nbp * 2 + 0], pa, vf);
                    mma16816(acc[nbp * 2 + 1], pa, vf + 2);
                }
            }
        }

        // ensure group jt+1 complete (per-thread) before next barrier
        if (jt + 1 < NTJ) {
            if (jt + 2 < NTJ) { CP_WAIT1; } else { CP_WAIT0; }
        }
    }

    // ---- l: in-warp shfl, then cross-wc reduction via smem ----
    float* lbuf = (float*)(sm + SM_PS);    // [4 wc][64 rows] (P dead)
    {
        l0 += __shfl_xor_sync(0xffffffffu, l0, 1);
        l0 += __shfl_xor_sync(0xffffffffu, l0, 2);
        l1 += __shfl_xor_sync(0xffffffffu, l1, 1);
        l1 += __shfl_xor_sync(0xffffffffu, l1, 2);
    }
    __syncthreads();                       // P reads done before overwrite
    if ((l & 3) == 0) {
        lbuf[wc * 64 + wr * 16 + (l >> 2)]     = l0;
        lbuf[wc * 64 + wr * 16 + (l >> 2) + 8] = l1;
    }
    __syncthreads();
    {
        const int r0 = wr * 16 + (l >> 2);
        float s0 = lbuf[r0] + lbuf[64 + r0] + lbuf[128 + r0] + lbuf[192 + r0];
        float s1 = lbuf[r0 + 8] + lbuf[64 + r0 + 8] + lbuf[128 + r0 + 8] + lbuf[192 + r0 + 8];
        const float gmma = gamma_p[0];
        const float inv0 = gmma / s0;
        const float inv1 = gmma / s1;
#pragma unroll
        for (int nb = 0; nb < 8; ++nb) {
            acc[nb][0] *= inv0;
            acc[nb][1] *= inv0;
            acc[nb][2] *= inv1;
            acc[nb][3] *= inv1;
        }
    }

    // ---- epilogue: 4 chunks of 64 ch, transpose through smem ----
    float* buf = (float*)(sm + SM_VS);     // 64 x 68 floats
    const int qr = l >> 2;
    const int qc = (l & 3) * 2;
#pragma unroll 1
    for (int cc = 0; cc < 4; ++cc) {
        __syncthreads();
        if (wc == cc) {
            const int ir = wr * 16 + qr;
#pragma unroll
            for (int nb = 0; nb < 8; ++nb) {
                int cl = nb * 8 + qc;
                buf[cl * 68 + ir]           = acc[nb][0];
                buf[(cl + 1) * 68 + ir]     = acc[nb][1];
                buf[cl * 68 + ir + 8]       = acc[nb][2];
                buf[(cl + 1) * 68 + ir + 8] = acc[nb][3];
            }
        }
        __syncthreads();
#pragma unroll
        for (int k2 = 0; k2 < 2; ++k2) {
            int e = tid + k2 * 512;
            int cl = e >> 4, seg = e & 15;
            float4 bv = *(float4*)(buf + cl * 68 + seg * 4);
            size_t g = ((size_t)(b * C + cc * 64 + cl)) * N + i0 + seg * 4;
            float4 fv = *(const float4*)(feat + g);
            float4 ov = {fv.x + bv.x, fv.y + bv.y, fv.z + bv.z, fv.w + bv.w};
            *(float4*)(out + g) = ov;
        }
    }
}

// ---------------------------------------------------------------------------
extern "C" void kernel_launch(void* const* d_in, const int* in_sizes, int n_in,
                              void* d_out, int out_size)
{
    const float* feat  = (const float*)d_in[0];
    const float* w1    = (const float*)d_in[1];
    const float* b1    = (const float*)d_in[2];
    const float* w2    = (const float*)d_in[3];
    const float* b2    = (const float*)d_in[4];
    const float* w3    = (const float*)d_in[5];
    const float* b3    = (const float*)d_in[6];
    const float* gamma = (const float*)d_in[7];
    float* out = (float*)d_out;

    cudaFuncSetAttribute(proj_mma_kernel, cudaFuncAttributeMaxDynamicSharedMemorySize, PJ_SMEM);
    proj_mma_kernel<<<dim3(N / PJ_N, B), 256, PJ_SMEM>>>(feat, w1, b1, w2, b2, w3, b3);

    cudaFuncSetAttribute(attn_kernel, cudaFuncAttributeMaxDynamicSharedMemorySize, SM_TOTAL);
    attn_kernel<<<dim3(N / TI, B), 512, SM_TOTAL>>>(feat, gamma, out);
}